// round 4
// baseline (speedup 1.0000x reference)
#include <cuda_runtime.h>
#include <cstdint>

// ModConv1x1: out[b,o,hw] = sum_c (weight[o,c]*style[b,c]) * x[b,c,hw]
// 16 batched GEMMs, M=128 N=4096 K=512, fp32.
// Strategy: tiled SGEMM, block tile 128(M) x 128(N), K-step 16, double-buffered
// SMEM, 8x8 per-thread microtile accumulated in packed f32x2 (fma.rn.f32x2,
// 2x fp32 FMA throughput vs scalar FFMA on sm_103a).

typedef unsigned long long u64;

constexpr int BATCH = 16;
constexpr int CIN   = 512;   // K
constexpr int COUT  = 128;   // M
constexpr int HW    = 64 * 64; // N = 4096
constexpr int KSTEP = 16;
constexpr int NTILE = 128;
constexpr int NKT   = CIN / KSTEP; // 32

__global__ __launch_bounds__(256, 2)
void modconv1x1_kernel(const float* __restrict__ x,
                       const float* __restrict__ style,
                       const float* __restrict__ weight,
                       float* __restrict__ out)
{
    __shared__ __align__(16) float a_s[2][KSTEP][COUT];   // modulated weight, [k][o]
    __shared__ __align__(16) float b_s[2][KSTEP][NTILE];  // x tile, [k][n]
    __shared__ __align__(16) float style_s[CIN];

    const int t  = threadIdx.x;        // 0..255
    const int b  = blockIdx.y;         // batch
    const int n0 = blockIdx.x * NTILE; // pixel tile origin

    // ---- style[b,:] -> smem (512 floats via 256 x float2)
    ((float2*)style_s)[t] = ((const float2*)(style + (size_t)b * CIN))[t];

    // ---- staging thread mapping
    const int wo = t & 63;          // weight row within half (o)
    const int wc = t >> 6;          // 0..3 : which float4 along k
    const int xk = t >> 5;          // 0..7 : x row within half of K-step
    const int xc = (t & 31) * 4;    // x column (float index), coalesced

    const float* xb = x + (size_t)b * CIN * HW + n0;

    float4 wreg[2], xreg[2];

    // prefetch k-step 0 (does not need style_s)
    #pragma unroll
    for (int g = 0; g < 2; ++g) {
        wreg[g] = *(const float4*)(weight + (size_t)(wo + g * 64) * CIN + wc * 4);
        xreg[g] = *(const float4*)(xb + (size_t)(xk + g * 8) * HW + xc);
    }
    __syncthreads();   // style_s ready for modulation below

    // stage buffer 0
    #pragma unroll
    for (int g = 0; g < 2; ++g) {
        const int o = wo + g * 64;
        a_s[0][wc * 4 + 0][o] = wreg[g].x * style_s[wc * 4 + 0];
        a_s[0][wc * 4 + 1][o] = wreg[g].y * style_s[wc * 4 + 1];
        a_s[0][wc * 4 + 2][o] = wreg[g].z * style_s[wc * 4 + 2];
        a_s[0][wc * 4 + 3][o] = wreg[g].w * style_s[wc * 4 + 3];
        *(float4*)&b_s[0][xk + g * 8][xc] = xreg[g];
    }
    __syncthreads();

    // ---- compute thread mapping: 16x16 threads, each 8x8 microtile,
    // rows {tm*4..+3, 64+tm*4..+3}, cols {tn*4..+3, 64+tn*4..+3}
    // (4-float groups keep LDS.128 quarter-warp phases conflict-free)
    const int tm = t >> 4;   // 0..15
    const int tn = t & 15;   // 0..15

    u64 acc[8][4];           // [m][n-pair]; pairs 0,1 = cols tn*4+{01,23}; 2,3 = +64
    #pragma unroll
    for (int m = 0; m < 8; ++m)
        #pragma unroll
        for (int p = 0; p < 4; ++p) acc[m][p] = 0ull;

    #pragma unroll 1
    for (int kt = 0; kt < NKT; ++kt) {
        const int buf = kt & 1;
        const int k0n = (kt + 1) * KSTEP;

        // prefetch next K-step from GMEM into registers (overlaps compute)
        if (kt + 1 < NKT) {
            #pragma unroll
            for (int g = 0; g < 2; ++g) {
                wreg[g] = *(const float4*)(weight + (size_t)(wo + g * 64) * CIN + k0n + wc * 4);
                xreg[g] = *(const float4*)(xb + (size_t)(k0n + xk + g * 8) * HW + xc);
            }
        }

        // main FMA body: 16 k x (8m x 8n) = 1024 MACs/thread via 512 FFMA2
        #pragma unroll
        for (int kk = 0; kk < KSTEP; ++kk) {
            float4 a0 = *(const float4*)&a_s[buf][kk][tm * 4];
            float4 a1 = *(const float4*)&a_s[buf][kk][64 + tm * 4];
            ulonglong2 b0 = *(const ulonglong2*)&b_s[buf][kk][tn * 4];
            ulonglong2 b1 = *(const ulonglong2*)&b_s[buf][kk][64 + tn * 4];
            const float am[8] = {a0.x, a0.y, a0.z, a0.w, a1.x, a1.y, a1.z, a1.w};
            #pragma unroll
            for (int m = 0; m < 8; ++m) {
                u64 a2;
                asm("mov.b64 %0, {%1, %1};" : "=l"(a2) : "f"(am[m]));
                asm("fma.rn.f32x2 %0, %1, %2, %0;" : "+l"(acc[m][0]) : "l"(a2), "l"(b0.x));
                asm("fma.rn.f32x2 %0, %1, %2, %0;" : "+l"(acc[m][1]) : "l"(a2), "l"(b0.y));
                asm("fma.rn.f32x2 %0, %1, %2, %0;" : "+l"(acc[m][2]) : "l"(a2), "l"(b1.x));
                asm("fma.rn.f32x2 %0, %1, %2, %0;" : "+l"(acc[m][3]) : "l"(a2), "l"(b1.y));
            }
        }

        // stage next buffer (prev iter's end-sync guarantees buf^1 is free)
        if (kt + 1 < NKT) {
            const int nb = buf ^ 1;
            #pragma unroll
            for (int g = 0; g < 2; ++g) {
                const int o = wo + g * 64;
                a_s[nb][wc * 4 + 0][o] = wreg[g].x * style_s[k0n + wc * 4 + 0];
                a_s[nb][wc * 4 + 1][o] = wreg[g].y * style_s[k0n + wc * 4 + 1];
                a_s[nb][wc * 4 + 2][o] = wreg[g].z * style_s[k0n + wc * 4 + 2];
                a_s[nb][wc * 4 + 3][o] = wreg[g].w * style_s[k0n + wc * 4 + 3];
                *(float4*)&b_s[nb][xk + g * 8][xc] = xreg[g];
            }
        }
        __syncthreads();
    }

    // ---- epilogue: STG.128 per 4-column group, fully coalesced along hw
    float* ob = out + (size_t)b * COUT * HW + n0;
    #pragma unroll
    for (int m = 0; m < 8; ++m) {
        const int rm = (m < 4) ? (tm * 4 + m) : (64 + tm * 4 + (m - 4));
        float* orow = ob + (size_t)rm * HW;
        ulonglong2 v0; v0.x = acc[m][0]; v0.y = acc[m][1];
        ulonglong2 v1; v1.x = acc[m][2]; v1.y = acc[m][3];
        *(ulonglong2*)(orow + tn * 4)      = v0;
        *(ulonglong2*)(orow + 64 + tn * 4) = v1;
    }
}

extern "C" void kernel_launch(void* const* d_in, const int* in_sizes, int n_in,
                              void* d_out, int out_size)
{
    const float* x      = (const float*)d_in[0];  // [16,512,64,64]
    const float* style  = (const float*)d_in[1];  // [16,512]
    const float* weight = (const float*)d_in[2];  // [128,512]
    float* out = (float*)d_out;                   // [16,128,64,64]

    dim3 grid(HW / NTILE, BATCH);  // 32 x 16 = 512 CTAs
    modconv1x1_kernel<<<grid, 256>>>(x, style, weight, out);
}

// round 7
// speedup vs baseline: 2.7883x; 2.7883x over previous
#include <cuda_runtime.h>
#include <cstdint>

// ModConv1x1 via mma.sync.m16n8k8 tf32 (plain sm_103 target — tcgen05 is
// 'a'-suffix gated and the harness compiles for sm_103 without it).
// out[b,o,hw] = sum_c (weight[o,c]*style[b,c]) * x[b,c,hw]
// Per CTA: 128(o) x 128(hw) tile, one batch, K=512 in 16 chunks of 32,
// double-buffered smem, fp32 accumulation in registers.

constexpr int CIN   = 512;
constexpr int COUT  = 128;
constexpr int HW    = 4096;
constexpr int NTILE = 128;
constexpr int KCHUNK  = 32;
constexpr int NCHUNKS = CIN / KCHUNK;   // 16
constexpr int THREADS = 256;

constexpr int APAD = 36;    // A row: 32 c + 4 pad (words)  -> frag bank = 4*gp+tg
constexpr int BPAD = 136;   // B row: 128 n + 8 pad (words) -> frag bank = 8*tg+gp

// dynamic smem layout in floats
constexpr int SM_STYLE_F = 0;                       // 512
constexpr int SM_A_F     = 512;                     // 2 * 128 * 36  = 9216
constexpr int SM_B_F     = 512 + 2 * COUT * APAD;   // 2 * 32 * 136  = 8704
constexpr int SM_TOTAL_F = SM_B_F + 2 * KCHUNK * BPAD;
constexpr int SM_TOTAL   = SM_TOTAL_F * 4;          // 73728 B

__device__ __forceinline__ float f2tf(float f) {
    uint32_t r;
    asm("cvt.rna.tf32.f32 %0, %1;" : "=r"(r) : "f"(f));
    return __uint_as_float(r);
}

__global__ __launch_bounds__(THREADS, 2)
void modconv_mma(const float* __restrict__ x,
                 const float* __restrict__ style,
                 const float* __restrict__ weight,
                 float* __restrict__ out)
{
    extern __shared__ float smem[];
    float* style_s = smem + SM_STYLE_F;
    float* A_s     = smem + SM_A_F;     // [2][COUT][APAD]
    float* B_s     = smem + SM_B_F;     // [2][KCHUNK][BPAD]

    const int t  = threadIdx.x;
    const int b  = blockIdx.y;
    const int n0 = blockIdx.x * NTILE;

    // style[b,:] -> smem (512 floats)
    ((float2*)style_s)[t] = ((const float2*)(style + (size_t)b * CIN))[t];

    const float* xb = x + (size_t)b * CIN * HW + n0;

    // ---- staging maps
    // A: per pass j (0..3): thread covers weight[o][c0 + 4*acq .. +4)
    const int acq = t & 7;           // c-quad within chunk (0..7)
    const int ao0 = t >> 3;          // o row base (0..31), +32*j
    // B: thread covers x[c0+bk][4*(bq0+8j) .. +4)
    const int bk  = t >> 3;          // k row (0..31)
    const int bq0 = t & 7;           // n-quad base, step 8

    __syncthreads();   // style ready

    // ---- stage chunk 0 into buffer 0
    {
        float* Ab = A_s;
        float* Bb = B_s;
        #pragma unroll
        for (int j = 0; j < 4; ++j) {
            const int o = ao0 + 32 * j;
            float4 w = *(const float4*)(weight + (size_t)o * CIN + 4 * acq);
            const int c = 4 * acq;
            float4 av;
            av.x = f2tf(w.x * style_s[c + 0]);
            av.y = f2tf(w.y * style_s[c + 1]);
            av.z = f2tf(w.z * style_s[c + 2]);
            av.w = f2tf(w.w * style_s[c + 3]);
            *(float4*)(Ab + o * APAD + c) = av;

            const int q = bq0 + 8 * j;
            float4 xv = *(const float4*)(xb + (size_t)bk * HW + 4 * q);
            float4 bv;
            bv.x = f2tf(xv.x); bv.y = f2tf(xv.y); bv.z = f2tf(xv.z); bv.w = f2tf(xv.w);
            *(float4*)(Bb + bk * BPAD + 4 * q) = bv;
        }
    }
    __syncthreads();

    // ---- compute maps: 8 warps = 2(M) x 4(N); warp tile 64(o) x 32(n)
    const int lane = t & 31, wid = t >> 5;
    const int mB = (wid >> 2) * 64;
    const int nB = (wid & 3) * 32;
    const int gp = lane >> 2;   // group id (0..7)
    const int tg = lane & 3;    // thread-in-group (0..3)

    float acc[4][4][4];
    #pragma unroll
    for (int mt = 0; mt < 4; ++mt)
        #pragma unroll
        for (int nt = 0; nt < 4; ++nt)
            #pragma unroll
            for (int i = 0; i < 4; ++i) acc[mt][nt][i] = 0.f;

    #pragma unroll 1
    for (int kc = 0; kc < NCHUNKS; ++kc) {
        const int buf = kc & 1;
        const float* Ab = A_s + buf * COUT * APAD;
        const float* Bb = B_s + buf * KCHUNK * BPAD;
        const bool more = (kc + 1 < NCHUNKS);
        const int c0n = (kc + 1) * KCHUNK;

        // prefetch next x chunk into regs (DRAM latency hides under MMAs)
        float4 xv[4];
        if (more) {
            #pragma unroll
            for (int j = 0; j < 4; ++j)
                xv[j] = *(const float4*)(xb + (size_t)(c0n + bk) * HW + 4 * (bq0 + 8 * j));
        }

        // 4 k8-steps: 16 LDS(A) + 8 LDS(B) + 16 MMA each
        #pragma unroll
        for (int ks = 0; ks < 4; ++ks) {
            const int kk = ks * 8;
            uint32_t a[4][4], bf[4][2];
            #pragma unroll
            for (int mt = 0; mt < 4; ++mt) {
                const float* ap = Ab + (size_t)(mB + mt * 16 + gp) * APAD + kk + tg;
                a[mt][0] = __float_as_uint(ap[0]);           // (m=gp,   k=tg)
                a[mt][1] = __float_as_uint(ap[8 * APAD]);    // (m=gp+8, k=tg)
                a[mt][2] = __float_as_uint(ap[4]);           // (m=gp,   k=tg+4)
                a[mt][3] = __float_as_uint(ap[8 * APAD + 4]);
            }
            #pragma unroll
            for (int nt = 0; nt < 4; ++nt) {
                const float* bp = Bb + (size_t)(kk + tg) * BPAD + nB + nt * 8 + gp;
                bf[nt][0] = __float_as_uint(bp[0]);          // (k=tg,   n=gp)
                bf[nt][1] = __float_as_uint(bp[4 * BPAD]);   // (k=tg+4, n=gp)
            }
            #pragma unroll
            for (int mt = 0; mt < 4; ++mt)
                #pragma unroll
                for (int nt = 0; nt < 4; ++nt) {
                    asm volatile(
                        "mma.sync.aligned.m16n8k8.row.col.f32.tf32.tf32.f32 "
                        "{%0,%1,%2,%3}, {%4,%5,%6,%7}, {%8,%9}, {%0,%1,%2,%3};"
                        : "+f"(acc[mt][nt][0]), "+f"(acc[mt][nt][1]),
                          "+f"(acc[mt][nt][2]), "+f"(acc[mt][nt][3])
                        : "r"(a[mt][0]), "r"(a[mt][1]), "r"(a[mt][2]), "r"(a[mt][3]),
                          "r"(bf[nt][0]), "r"(bf[nt][1]));
                }
        }

        // stage chunk k+1 into the other buffer
        if (more) {
            float* An = A_s + (buf ^ 1) * COUT * APAD;
            float* Bn = B_s + (buf ^ 1) * KCHUNK * BPAD;
            #pragma unroll
            for (int j = 0; j < 4; ++j) {
                const int o = ao0 + 32 * j;
                float4 w = *(const float4*)(weight + (size_t)o * CIN + c0n + 4 * acq);
                const int c = 4 * acq;
                float4 av;
                av.x = f2tf(w.x * style_s[c0n + c + 0]);
                av.y = f2tf(w.y * style_s[c0n + c + 1]);
                av.z = f2tf(w.z * style_s[c0n + c + 2]);
                av.w = f2tf(w.w * style_s[c0n + c + 3]);
                *(float4*)(An + o * APAD + c) = av;

                float4 bv;
                bv.x = f2tf(xv[j].x); bv.y = f2tf(xv[j].y);
                bv.z = f2tf(xv[j].z); bv.w = f2tf(xv[j].w);
                *(float4*)(Bn + bk * BPAD + 4 * (bq0 + 8 * j)) = bv;
            }
        }
        __syncthreads();
    }

    // ---- epilogue: c-frag rows are o, cols are hw -> direct STG.64
    float* ob = out + (size_t)b * COUT * HW + n0;
    #pragma unroll
    for (int mt = 0; mt < 4; ++mt) {
        const int o0 = mB + mt * 16 + gp;
        #pragma unroll
        for (int nt = 0; nt < 4; ++nt) {
            const int col = nB + nt * 8 + 2 * tg;
            *(float2*)(ob + (size_t)o0 * HW + col) =
                make_float2(acc[mt][nt][0], acc[mt][nt][1]);
            *(float2*)(ob + (size_t)(o0 + 8) * HW + col) =
                make_float2(acc[mt][nt][2], acc[mt][nt][3]);
        }
    }
}

extern "C" void kernel_launch(void* const* d_in, const int* in_sizes, int n_in,
                              void* d_out, int out_size)
{
    const float* x      = (const float*)d_in[0];  // [16,512,64,64]
    const float* style  = (const float*)d_in[1];  // [16,512]
    const float* weight = (const float*)d_in[2];  // [128,512]
    float* out = (float*)d_out;                   // [16,128,64,64]

    cudaFuncSetAttribute(modconv_mma, cudaFuncAttributeMaxDynamicSharedMemorySize, SM_TOTAL);
    dim3 grid(HW / NTILE, 16);                    // 32 x 16 = 512 CTAs
    modconv_mma<<<grid, THREADS, SM_TOTAL>>>(x, style, weight, out);
}